// round 2
// baseline (speedup 1.0000x reference)
#include <cuda_runtime.h>
#include <math.h>

// Problem constants
#define PB   128
#define PU   4
#define PNBS 64
#define PS   408

constexpr int S4     = PS / 4;                    // 102 float4 per row
constexpr int NAROW  = PB * PU;                   // 512
constexpr int TOT    = PB * PU * PNBS * PS;       // 13,369,344 elements
constexpr int AT     = PB * PU * PS;              // 208,896 elements
constexpr int AT4    = AT / 4;                    // 52,224 float4
constexpr int NSPLIT = 4;                         // nbs dimension split
constexpr int NBSPER = PNBS / NSPLIT;             // 16 nbs per task
constexpr int NTASK  = NAROW * NSPLIT * S4;       // 208,896 tasks
constexpr int NTHR   = 256;
constexpr int NBLK   = NTASK / NTHR;              // 816 blocks (exact)

// Global accumulators + arrival counter (zero-initialized at module load;
// last block resets them each run -> graph-replay safe, no allocs).
__device__ double       g_recv;
__device__ double       g_emr;
__device__ double       g_ema;
__device__ unsigned int g_count;

__device__ __forceinline__ float warp_reduce(float v) {
    #pragma unroll
    for (int off = 16; off > 0; off >>= 1)
        v += __shfl_down_sync(0xffffffffu, v, off);
    return v;
}

__global__ __launch_bounds__(NTHR, 8)
void prism_fused_kernel(const float4* __restrict__ a_re_g,
                        const float4* __restrict__ a_im_g,
                        const float4* __restrict__ r_re_g,
                        const float4* __restrict__ r_im_g,
                        const float4* __restrict__ t_re_g,
                        const float4* __restrict__ t_im_g,
                        const float4* __restrict__ w_g,
                        float* __restrict__ out) {
    const int tid = blockIdx.x * NTHR + threadIdx.x;

    float recv = 0.0f;   // sum(se * w)
    float emr  = 0.0f;   // sum(relu(|rad|-10)^2)
    float ema  = 0.0f;   // sum(relu(|atten|-1)^2)

    // ---- main stream: each thread owns one (arow, split, s4) task ----
    // task layout: tid = (arow * NSPLIT + split) * S4 + s4
    //   -> consecutive threads = consecutive s4 = coalesced 512B/warp.
    {
        const int s4    = tid % S4;
        const int rest  = tid / S4;
        const int split = rest % NSPLIT;
        const int arow  = rest / NSPLIT;

        // invariant loads: once per 16 streamed iterations (L2-resident)
        const float4 are = __ldg(&a_re_g[arow * S4 + s4]);
        const float4 aim = __ldg(&a_im_g[arow * S4 + s4]);
        const float4 wv  = __ldg(&w_g[s4]);

        const int row0 = arow * PNBS + split * NBSPER;
        long base = (long)row0 * S4 + s4;

        #pragma unroll 4
        for (int i = 0; i < NBSPER; i++) {
            const long v = base + (long)i * S4;
            const float4 rre = r_re_g[v];
            const float4 rim = r_im_g[v];
            const float4 tre = t_re_g[v];
            const float4 tim = t_im_g[v];

            #define PRISM_LANE(C)                                           \
            {                                                               \
                float pr = fmaf(are.C, rre.C, -(aim.C * rim.C));            \
                float pi = fmaf(are.C, rim.C,  (aim.C * rre.C));            \
                float dr = pr - tre.C;                                      \
                float di = pi - tim.C;                                      \
                float se = fmaf(dr, dr, di * di);                           \
                recv = fmaf(se, wv.C, recv);                                \
                float m2 = fmaf(rre.C, rre.C, rim.C * rim.C);               \
                if (m2 > 100.0f) {                                          \
                    float d = sqrtf(m2) - 10.0f;                            \
                    emr = fmaf(d, d, emr);                                  \
                }                                                           \
            }
            PRISM_LANE(x) PRISM_LANE(y) PRISM_LANE(z) PRISM_LANE(w)
            #undef PRISM_LANE
        }
    }

    // ---- atten EM term: one float4 per thread for tid < AT4 (L2-resident) ----
    if (tid < AT4) {
        const float4 are = a_re_g[tid];
        const float4 aim = a_im_g[tid];
        #define ATTEN_LANE(C)                                               \
        {                                                                   \
            float m2 = fmaf(are.C, are.C, aim.C * aim.C);                   \
            if (m2 > 1.0f) {                                                \
                float d = sqrtf(m2) - 1.0f;                                 \
                ema = fmaf(d, d, ema);                                      \
            }                                                               \
        }
        ATTEN_LANE(x) ATTEN_LANE(y) ATTEN_LANE(z) ATTEN_LANE(w)
        #undef ATTEN_LANE
    }

    // ---- block reduce ----
    __shared__ float s_recv[8], s_emr[8], s_ema[8];
    const int lane = threadIdx.x & 31;
    const int wid  = threadIdx.x >> 5;

    recv = warp_reduce(recv);
    emr  = warp_reduce(emr);
    ema  = warp_reduce(ema);
    if (lane == 0) { s_recv[wid] = recv; s_emr[wid] = emr; s_ema[wid] = ema; }
    __syncthreads();

    if (wid == 0) {
        recv = (lane < 8) ? s_recv[lane] : 0.0f;
        emr  = (lane < 8) ? s_emr[lane]  : 0.0f;
        ema  = (lane < 8) ? s_ema[lane]  : 0.0f;
        recv = warp_reduce(recv);
        emr  = warp_reduce(emr);
        ema  = warp_reduce(ema);

        if (lane == 0) {
            atomicAdd(&g_recv, (double)recv);
            atomicAdd(&g_emr,  (double)emr);
            atomicAdd(&g_ema,  (double)ema);
            __threadfence();
            // self-wrapping arrival counter: returns to 0 when last block arrives
            unsigned int prev = atomicInc(&g_count, NBLK - 1);
            if (prev == NBLK - 1) {
                // last block: all atomicAdds globally visible (fence + acquire via atomic)
                double rv = *((volatile double*)&g_recv);
                double er = *((volatile double*)&g_emr);
                double ea = *((volatile double*)&g_ema);
                out[0] = (float)(rv + 0.01 * (ea / (double)AT + er / (double)TOT));
                // reset for next graph replay
                g_recv = 0.0;
                g_emr  = 0.0;
                g_ema  = 0.0;
            }
        }
    }
}

extern "C" void kernel_launch(void* const* d_in, const int* in_sizes, int n_in,
                              void* d_out, int out_size) {
    const float4* a_re = (const float4*)d_in[0];
    const float4* a_im = (const float4*)d_in[1];
    const float4* r_re = (const float4*)d_in[2];
    const float4* r_im = (const float4*)d_in[3];
    const float4* t_re = (const float4*)d_in[4];
    const float4* t_im = (const float4*)d_in[5];
    const float4* w    = (const float4*)d_in[6];
    // d_in[7..10]: positions / ue_positions / view_directions / bs_antenna_ids — unused.

    prism_fused_kernel<<<NBLK, NTHR>>>(a_re, a_im, r_re, r_im, t_re, t_im, w,
                                       (float*)d_out);
}